// round 8
// baseline (speedup 1.0000x reference)
#include <cuda_runtime.h>
#include <cuda_bf16.h>

// LightConv: out[b,t,h*S+s] = sum_k softmax_k(filters[b,t,h*K+k]) * x[b, t+k-PAD, h*S+s] + bias[h*S+s]
// B=8 T=1024 H=8 S=64 K=31 C=512

#define B_ 8
#define T_ 1024
#define H_ 8
#define S_ 64
#define K_ 31
#define C_ 512
#define HK_ (H_ * K_)      // 248
#define PAD_ 15            // K/2
#define TTILE 128          // t rows per CTA
#define RT 8               // t outputs per thread
#define NTHREADS 256
#define XROWS (TTILE + 2 * PAD_)   // 158
#define WDSTRIDE 33        // u64 stride per t-row of duplicated weights (conflict-break pad)

// xs: 158*64*4 = 40448 B ; wd: 128*33*8 = 33792 B ; total 74240 B -> 3 CTAs/SM (222.7 KB)
#define SMEM_BYTES (XROWS * S_ * 4 + TTILE * WDSTRIDE * 8)

typedef unsigned long long u64;

__device__ __forceinline__ u64 pack2(float w) {
    u64 d;
    asm("mov.b64 %0, {%1, %1};" : "=l"(d) : "f"(w));
    return d;
}
__device__ __forceinline__ u64 pack2f(float a, float b) {
    u64 d;
    asm("mov.b64 %0, {%1, %2};" : "=l"(d) : "f"(a), "f"(b));
    return d;
}
__device__ __forceinline__ void fma2(u64& a, u64 x, u64 w) {
    asm("fma.rn.f32x2 %0, %1, %2, %3;" : "=l"(a) : "l"(x), "l"(w), "l"(a));
}
__device__ __forceinline__ float2 unpack2(u64 v) {
    float2 f;
    asm("mov.b64 {%0, %1}, %2;" : "=f"(f.x), "=f"(f.y) : "l"(v));
    return f;
}

__global__ __launch_bounds__(NTHREADS, 3) void lightconv_kernel(
    const float* __restrict__ x,
    const float* __restrict__ filters,
    const float* __restrict__ bias,
    float* __restrict__ out)
{
    extern __shared__ float smem[];
    float* xs = smem;                                        // [XROWS][64]
    u64*   wd = reinterpret_cast<u64*>(smem + XROWS * S_);   // [TTILE][WDSTRIDE] packed {w,w}

    const int t0   = blockIdx.x * TTILE;
    const int h    = blockIdx.y;
    const int b    = blockIdx.z;
    const int tid  = threadIdx.x;
    const int lane = tid & 31;
    const int warp = tid >> 5;

    // ---- load x tile with float4, zero-fill halo ----
    const float4* xbase4 = reinterpret_cast<const float4*>(x + (size_t)b * T_ * C_ + h * S_);
    float4* xs4w = reinterpret_cast<float4*>(xs);
    #pragma unroll 5
    for (int idx = tid; idx < XROWS * 16; idx += NTHREADS) {
        int row  = idx >> 4;
        int col4 = idx & 15;
        int t    = t0 + row - PAD_;
        float4 v = make_float4(0.f, 0.f, 0.f, 0.f);
        if (t >= 0 && t < T_) v = xbase4[(size_t)t * (C_ / 4) + col4];
        xs4w[idx] = v;
    }

    // ---- softmax over K=31 taps: warp per t-row, lane = k; 2 rows/iter ----
    // store duplicated {w,w} pairs t-major: wd[t][k]
    const float* fbase = filters + (size_t)b * T_ * HK_ + h * K_;
    for (int row = warp; row < TTILE; row += 16) {
        int rowB = row + 8;
        float fA = -1e30f, fB = -1e30f;
        if (lane < K_) {
            fA = fbase[(size_t)(t0 + row)  * HK_ + lane];
            fB = fbase[(size_t)(t0 + rowB) * HK_ + lane];
        }
        float mA = fA, mB = fB;
        #pragma unroll
        for (int o = 16; o > 0; o >>= 1) {
            mA = fmaxf(mA, __shfl_xor_sync(0xffffffffu, mA, o));
            mB = fmaxf(mB, __shfl_xor_sync(0xffffffffu, mB, o));
        }
        float eA = (lane < K_) ? __expf(fA - mA) : 0.0f;
        float eB = (lane < K_) ? __expf(fB - mB) : 0.0f;
        float sA = eA, sB = eB;
        #pragma unroll
        for (int o = 16; o > 0; o >>= 1) {
            sA += __shfl_xor_sync(0xffffffffu, sA, o);
            sB += __shfl_xor_sync(0xffffffffu, sB, o);
        }
        if (lane < K_) {
            wd[row  * WDSTRIDE + lane] = pack2(eA * (1.0f / sA));
            wd[rowB * WDSTRIDE + lane] = pack2(eB * (1.0f / sB));
        }
    }
    __syncthreads();

    // ---- main product ----
    // warp-pair t-group mapping: the warp's two halves are ADJACENT t-groups
    // (Delta row = 8), so the two 8B weight broadcasts land 16 banks apart
    // (8 * 33 u64 = 2112 B -> bank 16) -> 1 wavefront per weight LDS.64.
    const int s4 = lane & 15;
    const int tg = (warp << 1) | (lane >> 4);   // 0..15
    const int tl = tg * RT;

    const ulonglong2* xs2 = reinterpret_cast<const ulonglong2*>(xs) + s4;
    const u64* wrow = wd + tl * WDSTRIDE;   // weight (r, k=j-r) at wrow[r*WDSTRIDE + (j-r)]

    // init accumulators with bias
    float4 bv = reinterpret_cast<const float4*>(bias + h * S_)[s4];
    u64 acc[RT][2];
    #pragma unroll
    for (int r = 0; r < RT; ++r) {
        acc[r][0] = pack2f(bv.x, bv.y);
        acc[r][1] = pack2f(bv.z, bv.w);
    }

    // Region 1: j = 0 .. RT-2 (triangular, compile-time guards)
    #pragma unroll
    for (int j = 0; j < RT - 1; ++j) {
        ulonglong2 xv = xs2[(tl + j) * (S_ / 4)];
        #pragma unroll
        for (int r = 0; r < RT; ++r) {
            if (r <= j) {
                u64 w2 = wrow[r * WDSTRIDE + (j - r)];
                fma2(acc[r][0], xv.x, w2);
                fma2(acc[r][1], xv.y, w2);
            }
        }
    }

    // Region 2: j = RT-1 .. K-1 (steady state: 24 iters, no predicates, no movs)
    #pragma unroll 2
    for (int j = RT - 1; j < K_; ++j) {
        ulonglong2 xv = xs2[(tl + j) * (S_ / 4)];
        #pragma unroll
        for (int r = 0; r < RT; ++r) {
            u64 w2 = wrow[r * WDSTRIDE + (j - r)];
            fma2(acc[r][0], xv.x, w2);
            fma2(acc[r][1], xv.y, w2);
        }
    }

    // Region 3: j = K .. K+RT-2 (triangular, compile-time guards)
    #pragma unroll
    for (int j = K_; j < K_ + RT - 1; ++j) {
        ulonglong2 xv = xs2[(tl + j) * (S_ / 4)];
        #pragma unroll
        for (int r = 0; r < RT; ++r) {
            if (j - r < K_) {
                u64 w2 = wrow[r * WDSTRIDE + (j - r)];
                fma2(acc[r][0], xv.x, w2);
                fma2(acc[r][1], xv.y, w2);
            }
        }
    }

    // ---- epilogue: vectorized store (bias already folded in) ----
    float4* outbase = reinterpret_cast<float4*>(
        out + ((size_t)b * T_ + t0 + tl) * C_ + h * S_) + s4;
    #pragma unroll
    for (int r = 0; r < RT; ++r) {
        float2 lo = unpack2(acc[r][0]);
        float2 hi = unpack2(acc[r][1]);
        float4 o;
        o.x = lo.x;
        o.y = lo.y;
        o.z = hi.x;
        o.w = hi.y;
        outbase[(size_t)r * (C_ / 4)] = o;
    }
}

extern "C" void kernel_launch(void* const* d_in, const int* in_sizes, int n_in,
                              void* d_out, int out_size)
{
    const float* x       = (const float*)d_in[0];
    const float* filters = (const float*)d_in[1];
    const float* bias    = (const float*)d_in[2];
    float* out           = (float*)d_out;

    cudaFuncSetAttribute(lightconv_kernel,
                         cudaFuncAttributeMaxDynamicSharedMemorySize, SMEM_BYTES);

    dim3 grid(T_ / TTILE, H_, B_);   // (8, 8, 8) = 512 CTAs, 3 CTAs/SM
    lightconv_kernel<<<grid, NTHREADS, SMEM_BYTES>>>(x, filters, bias, out);
}

// round 10
// speedup vs baseline: 1.1419x; 1.1419x over previous
#include <cuda_runtime.h>
#include <cuda_bf16.h>

// LightConv: out[b,t,h*S+s] = sum_k softmax_k(filters[b,t,h*K+k]) * x[b, t+k-PAD, h*S+s] + bias[h*S+s]
// B=8 T=1024 H=8 S=64 K=31 C=512

#define B_ 8
#define T_ 1024
#define H_ 8
#define S_ 64
#define K_ 31
#define C_ 512
#define HK_ (H_ * K_)      // 248
#define PAD_ 15            // K/2
#define TTILE 128          // t rows per CTA
#define RT 8               // t outputs per thread
#define NTHREADS 256
#define XROWS (TTILE + 2 * PAD_)   // 158

// weights t-major: row t at float offset WROW(t) = t*36 + ((t>>3)&1)*4
//  - 36 floats = 144 B rows: 16B-aligned for LDS.128
//  - +16B swizzle per group-of-8 keeps the warp's two broadcast rows (Delta=8)
//    4 banks apart -> conflict-free broadcasts
#define WROW(t) ((t) * 36 + (((t) >> 3) & 1) * 4)
#define WD_FLOATS (WROW(TTILE - 1) + 36)          // 4612
#define SMEM_BYTES (XROWS * S_ * 4 + WD_FLOATS * 4)   // 40448 + 18448 = 58896 -> 3 CTAs/SM

typedef unsigned long long u64;

__device__ __forceinline__ u64 pack2(float w) {
    u64 d;
    asm("mov.b64 %0, {%1, %1};" : "=l"(d) : "f"(w));
    return d;
}
__device__ __forceinline__ u64 pack2f(float a, float b) {
    u64 d;
    asm("mov.b64 %0, {%1, %2};" : "=l"(d) : "f"(a), "f"(b));
    return d;
}
__device__ __forceinline__ void fma2(u64& a, u64 x, u64 w) {
    asm("fma.rn.f32x2 %0, %1, %2, %3;" : "=l"(a) : "l"(x), "l"(w), "l"(a));
}
__device__ __forceinline__ float2 unpack2(u64 v) {
    float2 f;
    asm("mov.b64 {%0, %1}, %2;" : "=f"(f.x), "=f"(f.y) : "l"(v));
    return f;
}

__global__ __launch_bounds__(NTHREADS, 3) void lightconv_kernel(
    const float* __restrict__ x,
    const float* __restrict__ filters,
    const float* __restrict__ bias,
    float* __restrict__ out)
{
    extern __shared__ float smem[];
    float* xs = smem;                    // [XROWS][64]
    float* wd = smem + XROWS * S_;       // t-major swizzled weight rows

    const int t0   = blockIdx.x * TTILE;
    const int h    = blockIdx.y;
    const int b    = blockIdx.z;
    const int tid  = threadIdx.x;
    const int lane = tid & 31;
    const int warp = tid >> 5;

    // ---- load x tile with float4, zero-fill halo ----
    const float4* xbase4 = reinterpret_cast<const float4*>(x + (size_t)b * T_ * C_ + h * S_);
    float4* xs4w = reinterpret_cast<float4*>(xs);
    #pragma unroll 5
    for (int idx = tid; idx < XROWS * 16; idx += NTHREADS) {
        int row  = idx >> 4;
        int col4 = idx & 15;
        int t    = t0 + row - PAD_;
        float4 v = make_float4(0.f, 0.f, 0.f, 0.f);
        if (t >= 0 && t < T_) v = xbase4[(size_t)t * (C_ / 4) + col4];
        xs4w[idx] = v;
    }

    // ---- softmax over K=31 taps: warp per t-row, lane = k; 2 rows/iter ----
    const float* fbase = filters + (size_t)b * T_ * HK_ + h * K_;
    for (int row = warp; row < TTILE; row += 16) {
        int rowB = row + 8;
        float fA = -1e30f, fB = -1e30f;
        if (lane < K_) {
            fA = fbase[(size_t)(t0 + row)  * HK_ + lane];
            fB = fbase[(size_t)(t0 + rowB) * HK_ + lane];
        }
        float mA = fA, mB = fB;
        #pragma unroll
        for (int o = 16; o > 0; o >>= 1) {
            mA = fmaxf(mA, __shfl_xor_sync(0xffffffffu, mA, o));
            mB = fmaxf(mB, __shfl_xor_sync(0xffffffffu, mB, o));
        }
        float eA = (lane < K_) ? __expf(fA - mA) : 0.0f;
        float eB = (lane < K_) ? __expf(fB - mB) : 0.0f;
        float sA = eA, sB = eB;
        #pragma unroll
        for (int o = 16; o > 0; o >>= 1) {
            sA += __shfl_xor_sync(0xffffffffu, sA, o);
            sB += __shfl_xor_sync(0xffffffffu, sB, o);
        }
        if (lane < K_) {
            wd[WROW(row)  + lane] = eA * (1.0f / sA);
            wd[WROW(rowB) + lane] = eB * (1.0f / sB);
        }
    }
    __syncthreads();

    // ---- main product ----
    const int s4 = tid & 15;
    const int tg = tid >> 4;
    const int tl = tg * RT;

    const ulonglong2* xs2 = reinterpret_cast<const ulonglong2*>(xs) + s4;

    // init accumulators with bias
    float4 bv = reinterpret_cast<const float4*>(bias + h * S_)[s4];
    u64 acc[RT][2];
    #pragma unroll
    for (int r = 0; r < RT; ++r) {
        acc[r][0] = pack2f(bv.x, bv.y);
        acc[r][1] = pack2f(bv.z, bv.w);
    }

    // Region 1: j = 0..7 triangular (scalar weight loads, compile-time guards)
    #pragma unroll
    for (int j = 0; j <= 7; ++j) {
        ulonglong2 xv = xs2[(tl + j) * (S_ / 4)];
        #pragma unroll
        for (int r = 0; r < RT; ++r) {
            if (r <= j) {
                u64 w2 = pack2(wd[WROW(tl + r) + (j - r)]);
                fma2(acc[r][0], xv.x, w2);
                fma2(acc[r][1], xv.y, w2);
            }
        }
    }

    // Register weight cache: wreg[r] holds chunk of 4 consecutive taps for output r.
    // Preload chunks current at j=8 for r not reloaded at j=8 (r=0 and r=4 reload there).
    float wreg[RT][4];
    #pragma unroll
    for (int r = 1; r <= 3; ++r)
        *reinterpret_cast<float4*>(wreg[r]) =
            *reinterpret_cast<const float4*>(wd + WROW(tl + r) + 4);
    #pragma unroll
    for (int r = 5; r <= 7; ++r)
        *reinterpret_cast<float4*>(wreg[r]) =
            *reinterpret_cast<const float4*>(wd + WROW(tl + r) + 0);

    // Region 2: steady state j = 8..30, fully unrolled (all indices static).
    // Per j: reload wreg[j&3] (chunk base j&~3) and wreg[(j&3)+4] (base (j&~3)-4).
    #pragma unroll
    for (int j = 8; j <= 30; ++j) {
        const int jj = j & 3;
        const int jb = j & ~3;
        *reinterpret_cast<float4*>(wreg[jj]) =
            *reinterpret_cast<const float4*>(wd + WROW(tl + jj) + jb);
        *reinterpret_cast<float4*>(wreg[jj + 4]) =
            *reinterpret_cast<const float4*>(wd + WROW(tl + jj + 4) + (jb - 4));
        ulonglong2 xv = xs2[(tl + j) * (S_ / 4)];
        #pragma unroll
        for (int r = 0; r < RT; ++r) {
            u64 w2 = pack2(wreg[r][(j - r) & 3]);
            fma2(acc[r][0], xv.x, w2);
            fma2(acc[r][1], xv.y, w2);
        }
    }

    // Region 3: j = 31..37 triangular (scalar weight loads, compile-time guards)
    #pragma unroll
    for (int j = K_; j < K_ + RT - 1; ++j) {
        ulonglong2 xv = xs2[(tl + j) * (S_ / 4)];
        #pragma unroll
        for (int r = 0; r < RT; ++r) {
            if (j - r < K_) {
                u64 w2 = pack2(wd[WROW(tl + r) + (j - r)]);
                fma2(acc[r][0], xv.x, w2);
                fma2(acc[r][1], xv.y, w2);
            }
        }
    }

    // ---- epilogue: vectorized store (bias already folded in) ----
    float4* outbase = reinterpret_cast<float4*>(
        out + ((size_t)b * T_ + t0 + tl) * C_ + h * S_) + s4;
    #pragma unroll
    for (int r = 0; r < RT; ++r) {
        float2 lo = unpack2(acc[r][0]);
        float2 hi = unpack2(acc[r][1]);
        float4 o;
        o.x = lo.x;
        o.y = lo.y;
        o.z = hi.x;
        o.w = hi.y;
        outbase[(size_t)r * (C_ / 4)] = o;
    }
}

extern "C" void kernel_launch(void* const* d_in, const int* in_sizes, int n_in,
                              void* d_out, int out_size)
{
    const float* x       = (const float*)d_in[0];
    const float* filters = (const float*)d_in[1];
    const float* bias    = (const float*)d_in[2];
    float* out           = (float*)d_out;

    cudaFuncSetAttribute(lightconv_kernel,
                         cudaFuncAttributeMaxDynamicSharedMemorySize, SMEM_BYTES);

    dim3 grid(T_ / TTILE, H_, B_);   // (8, 8, 8) = 512 CTAs, 3 CTAs/SM
    lightconv_kernel<<<grid, NTHREADS, SMEM_BYTES>>>(x, filters, bias, out);
}

// round 11
// speedup vs baseline: 1.1629x; 1.0184x over previous
#include <cuda_runtime.h>
#include <cuda_bf16.h>

// LightConv: out[b,t,h*S+s] = sum_k softmax_k(filters[b,t,h*K+k]) * x[b, t+k-PAD, h*S+s] + bias[h*S+s]
// B=8 T=1024 H=8 S=64 K=31 C=512

#define B_ 8
#define T_ 1024
#define H_ 8
#define S_ 64
#define K_ 31
#define C_ 512
#define HK_ (H_ * K_)      // 248
#define PAD_ 15            // K/2
#define TTILE 128          // t rows per CTA
#define RT 8               // t outputs per thread
#define NTHREADS 512       // 16 t-groups (= warps) x 32 channel-pair lanes
#define NGROUPS 16
#define XROWS (TTILE + 2 * PAD_)   // 158
#define DJ 38              // j slots (uniform band, zeros outside)
#define DSTRIDE (DJ * 8)   // 304 floats per t-group diag block (1216 B, 16B-aligned)

// xs: 158*64*4 = 40448 B ; diag: 16*304*4 = 19456 B ; total 59904 B -> 3 CTAs/SM (179.7 KB)
#define SMEM_BYTES (XROWS * S_ * 4 + NGROUPS * DSTRIDE * 4)

typedef unsigned long long u64;

__device__ __forceinline__ u64 pack2(float w) {
    u64 d;
    asm("mov.b64 %0, {%1, %1};" : "=l"(d) : "f"(w));
    return d;
}
__device__ __forceinline__ u64 pack2f(float a, float b) {
    u64 d;
    asm("mov.b64 %0, {%1, %2};" : "=l"(d) : "f"(a), "f"(b));
    return d;
}
__device__ __forceinline__ void fma2(u64& a, u64 x, u64 w) {
    asm("fma.rn.f32x2 %0, %1, %2, %3;" : "=l"(a) : "l"(x), "l"(w), "l"(a));
}
__device__ __forceinline__ float2 unpack2(u64 v) {
    float2 f;
    asm("mov.b64 {%0, %1}, %2;" : "=f"(f.x), "=f"(f.y) : "l"(v));
    return f;
}

__global__ __launch_bounds__(NTHREADS, 3) void lightconv_kernel(
    const float* __restrict__ x,
    const float* __restrict__ filters,
    const float* __restrict__ bias,
    float* __restrict__ out)
{
    extern __shared__ float smem[];
    float* xs   = smem;                    // [XROWS][64]
    float* diag = smem + XROWS * S_;       // [16 groups][38 j][8 r]

    const int t0   = blockIdx.x * TTILE;
    const int h    = blockIdx.y;
    const int b    = blockIdx.z;
    const int tid  = threadIdx.x;
    const int lane = tid & 31;
    const int warp = tid >> 5;

    // ---- load x tile with float4, zero-fill halo; zero diag (for band edges) ----
    const float4* xbase4 = reinterpret_cast<const float4*>(x + (size_t)b * T_ * C_ + h * S_);
    float4* xs4w = reinterpret_cast<float4*>(xs);
    #pragma unroll 3
    for (int idx = tid; idx < XROWS * 16; idx += NTHREADS) {
        int row  = idx >> 4;
        int col4 = idx & 15;
        int t    = t0 + row - PAD_;
        float4 v = make_float4(0.f, 0.f, 0.f, 0.f);
        if (t >= 0 && t < T_) v = xbase4[(size_t)t * (C_ / 4) + col4];
        xs4w[idx] = v;
    }
    #pragma unroll 5
    for (int i = tid; i < NGROUPS * DSTRIDE; i += NTHREADS)
        diag[i] = 0.0f;
    __syncthreads();

    // ---- softmax over K=31 taps: warp per t-row, lane = k; 2 rows/iter ----
    // scatter results straight into the diagonal layout:
    // weight (t-row, tap k) -> diag[row>>3][(k + (row&7)) * 8 + (row&7)]
    const float* fbase = filters + (size_t)b * T_ * HK_ + h * K_;
    #pragma unroll
    for (int base = warp; base < TTILE; base += 32) {
        int rowA = base, rowB = base + 16;
        float fA = -1e30f, fB = -1e30f;
        if (lane < K_) {
            fA = fbase[(size_t)(t0 + rowA) * HK_ + lane];
            fB = fbase[(size_t)(t0 + rowB) * HK_ + lane];
        }
        float mA = fA, mB = fB;
        #pragma unroll
        for (int o = 16; o > 0; o >>= 1) {
            mA = fmaxf(mA, __shfl_xor_sync(0xffffffffu, mA, o));
            mB = fmaxf(mB, __shfl_xor_sync(0xffffffffu, mB, o));
        }
        float eA = (lane < K_) ? __expf(fA - mA) : 0.0f;
        float eB = (lane < K_) ? __expf(fB - mB) : 0.0f;
        float sA = eA, sB = eB;
        #pragma unroll
        for (int o = 16; o > 0; o >>= 1) {
            sA += __shfl_xor_sync(0xffffffffu, sA, o);
            sB += __shfl_xor_sync(0xffffffffu, sB, o);
        }
        if (lane < K_) {
            int rA = rowA & 7, gA = rowA >> 3;
            int rB = rowB & 7, gB = rowB >> 3;
            diag[gA * DSTRIDE + (lane + rA) * 8 + rA] = eA * (1.0f / sA);
            diag[gB * DSTRIDE + (lane + rB) * 8 + rB] = eB * (1.0f / sB);
        }
    }
    __syncthreads();

    // ---- main product ----
    // warp = t-group of RT=8 rows; lane = channel pair (2 floats via f32x2)
    const int tg = warp;
    const int tl = tg * RT;

    const u64* xsg = reinterpret_cast<const u64*>(xs) + lane;  // element row*32 + lane
    const float* dg = diag + tg * DSTRIDE;

    // init accumulators with bias
    float2 bv = reinterpret_cast<const float2*>(bias + h * S_)[lane];
    u64 acc[RT];
    #pragma unroll
    for (int r = 0; r < RT; ++r) acc[r] = pack2f(bv.x, bv.y);

    // uniform banded loop: j = 0..37; out-of-band weights are exactly 0
    #pragma unroll
    for (int j = 0; j < DJ; ++j) {
        float4 wa = *reinterpret_cast<const float4*>(dg + j * 8);      // r = 0..3 (broadcast)
        float4 wb = *reinterpret_cast<const float4*>(dg + j * 8 + 4);  // r = 4..7 (broadcast)
        u64 xv = xsg[(tl + j) * 32];
        fma2(acc[0], xv, pack2(wa.x));
        fma2(acc[1], xv, pack2(wa.y));
        fma2(acc[2], xv, pack2(wa.z));
        fma2(acc[3], xv, pack2(wa.w));
        fma2(acc[4], xv, pack2(wb.x));
        fma2(acc[5], xv, pack2(wb.y));
        fma2(acc[6], xv, pack2(wb.z));
        fma2(acc[7], xv, pack2(wb.w));
    }

    // ---- epilogue: coalesced float2 stores (bias already folded in) ----
    float* obase = out + ((size_t)b * T_ + t0 + tl) * C_ + h * S_;
    #pragma unroll
    for (int r = 0; r < RT; ++r) {
        float2 o = unpack2(acc[r]);
        reinterpret_cast<float2*>(obase + (size_t)r * C_)[lane] = o;
    }
}

extern "C" void kernel_launch(void* const* d_in, const int* in_sizes, int n_in,
                              void* d_out, int out_size)
{
    const float* x       = (const float*)d_in[0];
    const float* filters = (const float*)d_in[1];
    const float* bias    = (const float*)d_in[2];
    float* out           = (float*)d_out;

    cudaFuncSetAttribute(lightconv_kernel,
                         cudaFuncAttributeMaxDynamicSharedMemorySize, SMEM_BYTES);

    dim3 grid(T_ / TTILE, H_, B_);   // (8, 8, 8) = 512 CTAs, 3x512-thread CTAs/SM
    lightconv_kernel<<<grid, NTHREADS, SMEM_BYTES>>>(x, filters, bias, out);
}